// round 1
// baseline (speedup 1.0000x reference)
#include <cuda_runtime.h>
#include <cstdint>

// Problem constants (fixed by dataset)
#define Nn 50000
#define Dd 128
#define Rr 3
#define Ee 800000
#define OUTD 64
#define ALPHAc 0.5f
#define BETA1c 0.6931471805599453f   // ln 2
#define BETA2c 0.4054651081081644f   // ln 1.5
#define SLOPEc 0.01f

// ---------------- scratch (device globals; no allocations allowed) ----------
__device__ float g_agg1[(size_t)Rr * Nn * Dd];   // 76.8 MB
__device__ float g_agg2[(size_t)Rr * Nn * Dd];   // 76.8 MB
__device__ float g_h1[(size_t)Nn * Dd];          // 25.6 MB
__device__ int   g_deg_out[Rr * Nn];
__device__ int   g_deg_in[Rr * Nn];
__device__ float g_dinv_out[Rr * Nn];
__device__ float g_dinv_in[Rr * Nn];
__device__ float g_G[Rr * Dd * OUTD];            // (1-a)/3 * M2_r
__device__ float g_Gx[Dd * OUTD];                // a/3 * sum_r M2_r
__device__ float g_c[OUTD];                      // bias term for output

// ---------------- zero scratch ----------------------------------------------
__global__ void k_zero() {
    size_t i0 = (size_t)blockIdx.x * blockDim.x + threadIdx.x;
    size_t stride = (size_t)gridDim.x * blockDim.x;
    const size_t n4 = (size_t)Rr * Nn * Dd / 4;
    float4 z = make_float4(0.f, 0.f, 0.f, 0.f);
    for (size_t i = i0; i < n4; i += stride) {
        reinterpret_cast<float4*>(g_agg1)[i] = z;
        reinterpret_cast<float4*>(g_agg2)[i] = z;
    }
    for (size_t i = i0; i < (size_t)Rr * Nn; i += stride) {
        g_deg_out[i] = 0;
        g_deg_in[i]  = 0;
    }
}

// ---------------- degree histogram -------------------------------------------
__global__ void k_degree(const int* __restrict__ src, const int* __restrict__ dst) {
    int i = blockIdx.x * blockDim.x + threadIdx.x;
    if (i >= Rr * Ee) return;
    int r = i / Ee;
    atomicAdd(&g_deg_out[r * Nn + src[i]], 1);
    atomicAdd(&g_deg_in [r * Nn + dst[i]], 1);
}

__global__ void k_dinv() {
    int i = blockIdx.x * blockDim.x + threadIdx.x;
    if (i >= Rr * Nn) return;
    int a = g_deg_out[i]; if (a < 1) a = 1;
    int b = g_deg_in[i];  if (b < 1) b = 1;
    g_dinv_out[i] = rsqrtf((float)a);
    g_dinv_in[i]  = rsqrtf((float)b);
}

// ---------------- precompute folded layer-2 matrices -------------------------
// M2_r = ((1-b2)I + b2*W2_r) @ Wlin  =  b2*(W2_r@Wlin) + (1-b2)*Wlin
__global__ void k_prep1(const float* __restrict__ W2, const float* __restrict__ Wlin) {
    int r = blockIdx.x;
    for (int o = threadIdx.x; o < Dd * OUTD; o += blockDim.x) {
        int i = o >> 6, j = o & 63;
        const float* wrow = W2 + ((size_t)r * Dd + i) * Dd;
        float s = 0.f;
        for (int k = 0; k < Dd; ++k) s += wrow[k] * Wlin[k * OUTD + j];
        g_G[r * Dd * OUTD + o] = BETA2c * s + (1.f - BETA2c) * Wlin[o];
    }
}

// Gx = a/3 * sum_r M2_r ; G_r *= (1-a)/3 ; c[j] = (mean_r b2_r) @ Wlin + blin
__global__ void k_prep2(const float* __restrict__ b2, const float* __restrict__ Wlin,
                        const float* __restrict__ blin) {
    int idx = blockIdx.x * blockDim.x + threadIdx.x;
    if (idx < Dd * OUTD) {
        float s = g_G[idx] + g_G[Dd * OUTD + idx] + g_G[2 * Dd * OUTD + idx];
        g_Gx[idx] = (ALPHAc / 3.f) * s;
        const float sc = (1.f - ALPHAc) / 3.f;
        g_G[idx] *= sc;
        g_G[Dd * OUTD + idx] *= sc;
        g_G[2 * Dd * OUTD + idx] *= sc;
    }
    if (idx < OUTD) {
        float cc = blin[idx];
        for (int k = 0; k < Dd; ++k)
            cc += (b2[k] + b2[Dd + k] + b2[2 * Dd + k]) * (1.f / 3.f) * Wlin[k * OUTD + idx];
        g_c[idx] = cc;
    }
}

// ---------------- SpMM scatter: agg[r][dst] += h[src]*dinv_out[r][src] -------
// one warp per edge; 32 lanes x float4 = 128 floats; vector red to L2
__global__ void k_scatter(const float* __restrict__ hin, const int* __restrict__ src,
                          const int* __restrict__ dst, int which) {
    int gw = (blockIdx.x * blockDim.x + threadIdx.x) >> 5;
    if (gw >= Rr * Ee) return;
    int lane = threadIdx.x & 31;
    int r = gw / Ee;
    const float* h = hin ? hin : (const float*)g_h1;
    float* agg = which ? g_agg2 : g_agg1;

    int s = __ldg(src + gw);
    int d = __ldg(dst + gw);
    float sc = g_dinv_out[r * Nn + s];
    float4 v = __ldg(reinterpret_cast<const float4*>(h + (size_t)s * Dd) + lane);
    v.x *= sc; v.y *= sc; v.z *= sc; v.w *= sc;
    float* p = agg + ((size_t)(r * Nn + d)) * Dd + lane * 4;
    asm volatile("red.global.add.v4.f32 [%0], {%1,%2,%3,%4};"
                 :: "l"(p), "f"(v.x), "f"(v.y), "f"(v.z), "f"(v.w) : "memory");
}

// ---------------- layer-1 fused node kernel ----------------------------------
// For a 64-node tile: for each relation r:
//   rst = (1-a)*agg1_r*dinv_in_r + a*x              (built into smem A)
//   t_r = leaky( b1*(rst@W1_r) + (1-b1)*rst + bias ) (reg-blocked GEMM)
//   h1 += t_r / 3
__launch_bounds__(256)
__global__ void k_node1(const float* __restrict__ x, const float* __restrict__ W1,
                        const float* __restrict__ b1) {
    __shared__ float As[64 * 132];     // 64 x 128, stride 132 (conflict-free)
    __shared__ float Ws[16 * 128];     // K-chunk of W
    int tid = threadIdx.x;
    int ty = tid >> 4, tx = tid & 15;  // 16x16 thread grid; tile 4 rows x 8 cols
    int n0 = blockIdx.x << 6;

    float hacc[4][8];
#pragma unroll
    for (int i = 0; i < 4; ++i)
#pragma unroll
        for (int j = 0; j < 8; ++j) hacc[i][j] = 0.f;

    for (int r = 0; r < Rr; ++r) {
        // build A tile = rst
        for (int idx = tid; idx < 64 * 32; idx += 256) {
            int row = idx >> 5, c4 = idx & 31;
            int n = n0 + row;
            float4 v = make_float4(0.f, 0.f, 0.f, 0.f);
            if (n < Nn) {
                float di = g_dinv_in[r * Nn + n] * (1.f - ALPHAc);
                float4 a = reinterpret_cast<const float4*>(g_agg1 + ((size_t)(r * Nn + n)) * Dd)[c4];
                float4 xv = reinterpret_cast<const float4*>(x + (size_t)n * Dd)[c4];
                v.x = di * a.x + ALPHAc * xv.x;
                v.y = di * a.y + ALPHAc * xv.y;
                v.z = di * a.z + ALPHAc * xv.z;
                v.w = di * a.w + ALPHAc * xv.w;
            }
            *reinterpret_cast<float4*>(&As[row * 132 + c4 * 4]) = v;
        }
        __syncthreads();

        float acc[4][8];
#pragma unroll
        for (int i = 0; i < 4; ++i)
#pragma unroll
            for (int j = 0; j < 8; ++j) acc[i][j] = 0.f;

        for (int kc = 0; kc < 8; ++kc) {
            for (int idx = tid; idx < 16 * 32; idx += 256) {
                int kr = idx >> 5, c4 = idx & 31;
                reinterpret_cast<float4*>(&Ws[kr * 128])[c4] =
                    reinterpret_cast<const float4*>(W1 + ((size_t)r * Dd + kc * 16 + kr) * Dd)[c4];
            }
            __syncthreads();
#pragma unroll
            for (int k = 0; k < 16; ++k) {
                float a[4];
#pragma unroll
                for (int i = 0; i < 4; ++i) a[i] = As[(ty * 4 + i) * 132 + kc * 16 + k];
                float4 w0 = *reinterpret_cast<float4*>(&Ws[k * 128 + tx * 8]);
                float4 w1 = *reinterpret_cast<float4*>(&Ws[k * 128 + tx * 8 + 4]);
#pragma unroll
                for (int i = 0; i < 4; ++i) {
                    acc[i][0] += a[i] * w0.x; acc[i][1] += a[i] * w0.y;
                    acc[i][2] += a[i] * w0.z; acc[i][3] += a[i] * w0.w;
                    acc[i][4] += a[i] * w1.x; acc[i][5] += a[i] * w1.y;
                    acc[i][6] += a[i] * w1.z; acc[i][7] += a[i] * w1.w;
                }
            }
            __syncthreads();
        }

        // epilogue: identity mapping + bias + leaky_relu + 1/3 mean
#pragma unroll
        for (int i = 0; i < 4; ++i) {
            int row = ty * 4 + i;
#pragma unroll
            for (int j = 0; j < 8; ++j) {
                int col = tx * 8 + j;
                float v = BETA1c * acc[i][j] + (1.f - BETA1c) * As[row * 132 + col]
                          + b1[r * Dd + col];
                v = v >= 0.f ? v : SLOPEc * v;
                hacc[i][j] += v * (1.f / 3.f);
            }
        }
        __syncthreads();
    }

#pragma unroll
    for (int i = 0; i < 4; ++i) {
        int n = n0 + ty * 4 + i;
        if (n < Nn) {
            float4 o0 = make_float4(hacc[i][0], hacc[i][1], hacc[i][2], hacc[i][3]);
            float4 o1 = make_float4(hacc[i][4], hacc[i][5], hacc[i][6], hacc[i][7]);
            float4* pp = reinterpret_cast<float4*>(g_h1 + (size_t)n * Dd + tx * 8);
            pp[0] = o0;
            pp[1] = o1;
        }
    }
}

// ---------------- layer-2 + output projection, fully folded ------------------
// out[n] = sum_r (agg2_r[n]*dinv_in_r[n]) @ G_r  +  x[n] @ Gx  +  c
__launch_bounds__(256)
__global__ void k_node2(const float* __restrict__ x, float* __restrict__ out) {
    __shared__ float As[64 * 132];
    __shared__ float Ws[16 * 64];
    int tid = threadIdx.x;
    int ty = tid >> 4, tx = tid & 15;  // tile 4 rows x 4 cols (64x64 out tile)
    int n0 = blockIdx.x << 6;

    float acc[4][4];
#pragma unroll
    for (int i = 0; i < 4; ++i)
#pragma unroll
        for (int j = 0; j < 4; ++j) acc[i][j] = 0.f;

    for (int seg = 0; seg < 4; ++seg) {
        for (int idx = tid; idx < 64 * 32; idx += 256) {
            int row = idx >> 5, c4 = idx & 31;
            int n = n0 + row;
            float4 v = make_float4(0.f, 0.f, 0.f, 0.f);
            if (n < Nn) {
                if (seg < 3) {
                    float di = g_dinv_in[seg * Nn + n];
                    float4 a = reinterpret_cast<const float4*>(g_agg2 + ((size_t)(seg * Nn + n)) * Dd)[c4];
                    v.x = a.x * di; v.y = a.y * di; v.z = a.z * di; v.w = a.w * di;
                } else {
                    v = reinterpret_cast<const float4*>(x + (size_t)n * Dd)[c4];
                }
            }
            *reinterpret_cast<float4*>(&As[row * 132 + c4 * 4]) = v;
        }
        __syncthreads();

        const float* B = (seg < 3) ? (const float*)(g_G + seg * Dd * OUTD) : (const float*)g_Gx;
        for (int kc = 0; kc < 8; ++kc) {
            {
                int kr = tid >> 4, c4 = tid & 15;   // 256 threads == 256 float4s
                reinterpret_cast<float4*>(&Ws[kr * 64])[c4] =
                    reinterpret_cast<const float4*>(B + (size_t)(kc * 16 + kr) * OUTD)[c4];
            }
            __syncthreads();
#pragma unroll
            for (int k = 0; k < 16; ++k) {
                float a[4];
#pragma unroll
                for (int i = 0; i < 4; ++i) a[i] = As[(ty * 4 + i) * 132 + kc * 16 + k];
                float4 w = *reinterpret_cast<float4*>(&Ws[k * 64 + tx * 4]);
#pragma unroll
                for (int i = 0; i < 4; ++i) {
                    acc[i][0] += a[i] * w.x; acc[i][1] += a[i] * w.y;
                    acc[i][2] += a[i] * w.z; acc[i][3] += a[i] * w.w;
                }
            }
            __syncthreads();
        }
    }

#pragma unroll
    for (int i = 0; i < 4; ++i) {
        int n = n0 + ty * 4 + i;
        if (n < Nn) {
            float4 o;
            o.x = acc[i][0] + g_c[tx * 4 + 0];
            o.y = acc[i][1] + g_c[tx * 4 + 1];
            o.z = acc[i][2] + g_c[tx * 4 + 2];
            o.w = acc[i][3] + g_c[tx * 4 + 3];
            *reinterpret_cast<float4*>(out + (size_t)n * OUTD + tx * 4) = o;
        }
    }
}

// ---------------- launch ------------------------------------------------------
extern "C" void kernel_launch(void* const* d_in, const int* in_sizes, int n_in,
                              void* d_out, int out_size) {
    const float* x    = (const float*)d_in[0];
    const int*   src  = (const int*)  d_in[1];
    const int*   dst  = (const int*)  d_in[2];
    const float* W1   = (const float*)d_in[3];
    const float* b1   = (const float*)d_in[4];
    const float* W2   = (const float*)d_in[5];
    const float* b2   = (const float*)d_in[6];
    const float* Wlin = (const float*)d_in[7];
    const float* blin = (const float*)d_in[8];
    float* out = (float*)d_out;

    k_zero<<<2048, 256>>>();
    k_degree<<<(Rr * Ee + 255) / 256, 256>>>(src, dst);
    k_dinv<<<(Rr * Nn + 255) / 256, 256>>>();
    k_prep1<<<3, 256>>>(W2, Wlin);
    k_prep2<<<32, 256>>>(b2, Wlin, blin);

    // layer 1
    k_scatter<<<(Rr * Ee) / 8, 256>>>(x, src, dst, 0);
    k_node1<<<(Nn + 63) / 64, 256>>>(x, W1, b1);

    // layer 2 (+ folded output projection)
    k_scatter<<<(Rr * Ee) / 8, 256>>>(nullptr, src, dst, 1);
    k_node2<<<(Nn + 63) / 64, 256>>>(x, out);
}

// round 2
// speedup vs baseline: 1.6752x; 1.6752x over previous
#include <cuda_runtime.h>
#include <cstdint>

// Problem constants (fixed by dataset)
#define Nn 50000
#define Dd 128
#define Rr 3
#define Ee 800000
#define OUTD 64
#define ALPHAc 0.5f
#define BETA1c 0.6931471805599453f   // ln 2
#define BETA2c 0.4054651081081644f   // ln 1.5
#define SLOPEc 0.01f

// ---------------- scratch (device globals; no allocations allowed) ----------
__device__ float g_h1[(size_t)Nn * Dd];          // 25.6 MB
__device__ int   g_deg_out[Rr * Nn];
__device__ int   g_deg_in[Rr * Nn];
__device__ float g_dinv_out[Rr * Nn];
__device__ float g_dinv_in[Rr * Nn];
__device__ int   g_rowstart[Rr * Nn];            // CSR-by-dst row starts
__device__ int   g_fillcur[Rr * Nn];             // fill cursors
__device__ int   g_col[(size_t)Rr * Ee];         // CSR col = src node (9.6 MB)
__device__ int   g_cursor[Rr];
__device__ float g_G[Rr * Dd * OUTD];            // (1-a)/3 * M2_r
__device__ float g_Gx[Dd * OUTD];                // a/3 * sum_r M2_r
__device__ float g_c[OUTD];                      // bias term for output

// ---------------- init small state -------------------------------------------
__global__ void k_init() {
    int i = blockIdx.x * blockDim.x + threadIdx.x;
    if (i < Rr * Nn) { g_deg_out[i] = 0; g_deg_in[i] = 0; }
    if (i < Rr) g_cursor[i] = 0;
}

// ---------------- degree histogram -------------------------------------------
__global__ void k_degree(const int* __restrict__ src, const int* __restrict__ dst) {
    int i = blockIdx.x * blockDim.x + threadIdx.x;
    if (i >= Rr * Ee) return;
    int r = i / Ee;
    atomicAdd(&g_deg_out[r * Nn + src[i]], 1);
    atomicAdd(&g_deg_in [r * Nn + dst[i]], 1);
}

// ---------------- row starts via warp-aggregated scan + dinv ------------------
__global__ void k_rowstart() {
    int r = blockIdx.y;
    int n = blockIdx.x * blockDim.x + threadIdx.x;
    int lane = threadIdx.x & 31;
    int d = (n < Nn) ? g_deg_in[r * Nn + n] : 0;
    // warp inclusive scan
    int incl = d;
#pragma unroll
    for (int o = 1; o < 32; o <<= 1) {
        int v = __shfl_up_sync(0xffffffffu, incl, o);
        if (lane >= o) incl += v;
    }
    int total = __shfl_sync(0xffffffffu, incl, 31);
    int base = 0;
    if (lane == 31) base = atomicAdd(&g_cursor[r], total);
    base = __shfl_sync(0xffffffffu, base, 31);
    if (n < Nn) {
        int start = r * Ee + base + incl - d;
        g_rowstart[r * Nn + n] = start;
        g_fillcur [r * Nn + n] = start;
        int di = d < 1 ? 1 : d;
        g_dinv_in[r * Nn + n] = rsqrtf((float)di);
        int doo = g_deg_out[r * Nn + n]; if (doo < 1) doo = 1;
        g_dinv_out[r * Nn + n] = rsqrtf((float)doo);
    }
}

// ---------------- CSR fill -----------------------------------------------------
__global__ void k_csrfill(const int* __restrict__ src, const int* __restrict__ dst) {
    int i = blockIdx.x * blockDim.x + threadIdx.x;
    if (i >= Rr * Ee) return;
    int r = i / Ee;
    int pos = atomicAdd(&g_fillcur[r * Nn + dst[i]], 1);
    g_col[pos] = src[i];
}

// ---------------- precompute folded layer-2 matrices --------------------------
// M2_r = ((1-b2)I + b2*W2_r) @ Wlin  =  b2*(W2_r@Wlin) + (1-b2)*Wlin
// grid = Rr*Dd blocks, 64 threads (one output element each)
__global__ void k_prep1(const float* __restrict__ W2, const float* __restrict__ Wlin) {
    int r = blockIdx.x >> 7;          // /128
    int i = blockIdx.x & 127;
    int j = threadIdx.x;              // 0..63
    const float* wrow = W2 + ((size_t)r * Dd + i) * Dd;
    float s = 0.f;
#pragma unroll 8
    for (int k = 0; k < Dd; ++k) s += wrow[k] * Wlin[k * OUTD + j];
    g_G[((size_t)r * Dd + i) * OUTD + j] = BETA2c * s + (1.f - BETA2c) * Wlin[i * OUTD + j];
}

// Gx = a/3 * sum_r M2_r ; G_r *= (1-a)/3 ; c[j] = (mean_r b2_r) @ Wlin + blin
__global__ void k_prep2(const float* __restrict__ b2, const float* __restrict__ Wlin,
                        const float* __restrict__ blin) {
    int idx = blockIdx.x * blockDim.x + threadIdx.x;
    if (idx < Dd * OUTD) {
        float s = g_G[idx] + g_G[Dd * OUTD + idx] + g_G[2 * Dd * OUTD + idx];
        g_Gx[idx] = (ALPHAc / 3.f) * s;
        const float sc = (1.f - ALPHAc) / 3.f;
        g_G[idx] *= sc;
        g_G[Dd * OUTD + idx] *= sc;
        g_G[2 * Dd * OUTD + idx] *= sc;
    }
    if (idx < OUTD) {
        float cc = blin[idx];
        for (int k = 0; k < Dd; ++k)
            cc += (b2[k] + b2[Dd + k] + b2[2 * Dd + k]) * (1.f / 3.f) * Wlin[k * OUTD + idx];
        g_c[idx] = cc;
    }
}

// ---------------- layer-1: fused gather + GEMM --------------------------------
// Per 64-node tile, per relation r:
//   agg[n]  = sum_{e in CSR[r][n]} x[col[e]] * dinv_out[r][col[e]]   (warp gather)
//   rst     = (1-a)*dinv_in*agg + a*x[n]                              (smem A)
//   t_r     = leaky( b1*(rst@W1_r) + (1-b1)*rst + bias )
//   h1     += t_r / 3
__launch_bounds__(256)
__global__ void k_node1(const float* __restrict__ x, const float* __restrict__ W1,
                        const float* __restrict__ b1) {
    __shared__ float As[64 * 132];
    __shared__ float Ws[16 * 128];
    int tid = threadIdx.x;
    int warp = tid >> 5, lane = tid & 31;
    int ty = tid >> 4, tx = tid & 15;
    int n0 = blockIdx.x << 6;

    float hacc[4][8];
#pragma unroll
    for (int i = 0; i < 4; ++i)
#pragma unroll
        for (int j = 0; j < 8; ++j) hacc[i][j] = 0.f;

    for (int r = 0; r < Rr; ++r) {
        // ---- fused gather: build As = rst
#pragma unroll 1
        for (int ii = 0; ii < 8; ++ii) {
            int row = warp * 8 + ii;
            int n = n0 + row;
            float4 v = make_float4(0.f, 0.f, 0.f, 0.f);
            if (n < Nn) {
                float4 acc = make_float4(0.f, 0.f, 0.f, 0.f);
                int beg = g_rowstart[r * Nn + n];
                int end = beg + g_deg_in[r * Nn + n];
                int e = beg;
                for (; e + 2 <= end; e += 2) {
                    int s0 = __ldg(g_col + e);
                    int s1 = __ldg(g_col + e + 1);
                    float sc0 = __ldg(g_dinv_out + r * Nn + s0);
                    float sc1 = __ldg(g_dinv_out + r * Nn + s1);
                    float4 h0 = __ldg(reinterpret_cast<const float4*>(x + (size_t)s0 * Dd) + lane);
                    float4 h1v = __ldg(reinterpret_cast<const float4*>(x + (size_t)s1 * Dd) + lane);
                    acc.x += sc0 * h0.x + sc1 * h1v.x;
                    acc.y += sc0 * h0.y + sc1 * h1v.y;
                    acc.z += sc0 * h0.z + sc1 * h1v.z;
                    acc.w += sc0 * h0.w + sc1 * h1v.w;
                }
                if (e < end) {
                    int s0 = __ldg(g_col + e);
                    float sc0 = __ldg(g_dinv_out + r * Nn + s0);
                    float4 h0 = __ldg(reinterpret_cast<const float4*>(x + (size_t)s0 * Dd) + lane);
                    acc.x += sc0 * h0.x; acc.y += sc0 * h0.y;
                    acc.z += sc0 * h0.z; acc.w += sc0 * h0.w;
                }
                float di = g_dinv_in[r * Nn + n] * (1.f - ALPHAc);
                float4 xv = __ldg(reinterpret_cast<const float4*>(x + (size_t)n * Dd) + lane);
                v.x = di * acc.x + ALPHAc * xv.x;
                v.y = di * acc.y + ALPHAc * xv.y;
                v.z = di * acc.z + ALPHAc * xv.z;
                v.w = di * acc.w + ALPHAc * xv.w;
            }
            *reinterpret_cast<float4*>(&As[row * 132 + lane * 4]) = v;
        }
        __syncthreads();

        // ---- register-blocked GEMM: rst @ W1_r
        float acc[4][8];
#pragma unroll
        for (int i = 0; i < 4; ++i)
#pragma unroll
            for (int j = 0; j < 8; ++j) acc[i][j] = 0.f;

        for (int kc = 0; kc < 8; ++kc) {
            for (int idx = tid; idx < 16 * 32; idx += 256) {
                int kr = idx >> 5, c4 = idx & 31;
                reinterpret_cast<float4*>(&Ws[kr * 128])[c4] =
                    reinterpret_cast<const float4*>(W1 + ((size_t)r * Dd + kc * 16 + kr) * Dd)[c4];
            }
            __syncthreads();
#pragma unroll
            for (int k = 0; k < 16; ++k) {
                float a[4];
#pragma unroll
                for (int i = 0; i < 4; ++i) a[i] = As[(ty * 4 + i) * 132 + kc * 16 + k];
                float4 w0 = *reinterpret_cast<float4*>(&Ws[k * 128 + tx * 8]);
                float4 w1 = *reinterpret_cast<float4*>(&Ws[k * 128 + tx * 8 + 4]);
#pragma unroll
                for (int i = 0; i < 4; ++i) {
                    acc[i][0] += a[i] * w0.x; acc[i][1] += a[i] * w0.y;
                    acc[i][2] += a[i] * w0.z; acc[i][3] += a[i] * w0.w;
                    acc[i][4] += a[i] * w1.x; acc[i][5] += a[i] * w1.y;
                    acc[i][6] += a[i] * w1.z; acc[i][7] += a[i] * w1.w;
                }
            }
            __syncthreads();
        }

        // epilogue: identity mapping + bias + leaky_relu + 1/3 mean
#pragma unroll
        for (int i = 0; i < 4; ++i) {
            int row = ty * 4 + i;
#pragma unroll
            for (int j = 0; j < 8; ++j) {
                int col = tx * 8 + j;
                float v = BETA1c * acc[i][j] + (1.f - BETA1c) * As[row * 132 + col]
                          + b1[r * Dd + col];
                v = v >= 0.f ? v : SLOPEc * v;
                hacc[i][j] += v * (1.f / 3.f);
            }
        }
        __syncthreads();
    }

#pragma unroll
    for (int i = 0; i < 4; ++i) {
        int n = n0 + ty * 4 + i;
        if (n < Nn) {
            float4 o0 = make_float4(hacc[i][0], hacc[i][1], hacc[i][2], hacc[i][3]);
            float4 o1 = make_float4(hacc[i][4], hacc[i][5], hacc[i][6], hacc[i][7]);
            float4* pp = reinterpret_cast<float4*>(g_h1 + (size_t)n * Dd + tx * 8);
            pp[0] = o0;
            pp[1] = o1;
        }
    }
}

// ---------------- layer-2 + output projection, fused gather -------------------
// out[n] = sum_r (gather_r(h1)[n]*dinv_in_r[n]) @ G_r  +  x[n] @ Gx  +  c
__launch_bounds__(256)
__global__ void k_node2(const float* __restrict__ x, float* __restrict__ out) {
    __shared__ float As[64 * 132];
    __shared__ float Ws[16 * 64];
    int tid = threadIdx.x;
    int warp = tid >> 5, lane = tid & 31;
    int ty = tid >> 4, tx = tid & 15;
    int n0 = blockIdx.x << 6;

    float acc[4][4];
#pragma unroll
    for (int i = 0; i < 4; ++i)
#pragma unroll
        for (int j = 0; j < 4; ++j) acc[i][j] = 0.f;

    for (int seg = 0; seg < 4; ++seg) {
        // ---- build As
#pragma unroll 1
        for (int ii = 0; ii < 8; ++ii) {
            int row = warp * 8 + ii;
            int n = n0 + row;
            float4 v = make_float4(0.f, 0.f, 0.f, 0.f);
            if (n < Nn) {
                if (seg < 3) {
                    int r = seg;
                    float4 a = make_float4(0.f, 0.f, 0.f, 0.f);
                    int beg = g_rowstart[r * Nn + n];
                    int end = beg + g_deg_in[r * Nn + n];
                    int e = beg;
                    for (; e + 2 <= end; e += 2) {
                        int s0 = __ldg(g_col + e);
                        int s1 = __ldg(g_col + e + 1);
                        float sc0 = __ldg(g_dinv_out + r * Nn + s0);
                        float sc1 = __ldg(g_dinv_out + r * Nn + s1);
                        float4 h0 = __ldg(reinterpret_cast<const float4*>(g_h1 + (size_t)s0 * Dd) + lane);
                        float4 h1v = __ldg(reinterpret_cast<const float4*>(g_h1 + (size_t)s1 * Dd) + lane);
                        a.x += sc0 * h0.x + sc1 * h1v.x;
                        a.y += sc0 * h0.y + sc1 * h1v.y;
                        a.z += sc0 * h0.z + sc1 * h1v.z;
                        a.w += sc0 * h0.w + sc1 * h1v.w;
                    }
                    if (e < end) {
                        int s0 = __ldg(g_col + e);
                        float sc0 = __ldg(g_dinv_out + r * Nn + s0);
                        float4 h0 = __ldg(reinterpret_cast<const float4*>(g_h1 + (size_t)s0 * Dd) + lane);
                        a.x += sc0 * h0.x; a.y += sc0 * h0.y;
                        a.z += sc0 * h0.z; a.w += sc0 * h0.w;
                    }
                    float di = g_dinv_in[r * Nn + n];
                    v.x = a.x * di; v.y = a.y * di; v.z = a.z * di; v.w = a.w * di;
                } else {
                    v = __ldg(reinterpret_cast<const float4*>(x + (size_t)n * Dd) + lane);
                }
            }
            *reinterpret_cast<float4*>(&As[row * 132 + lane * 4]) = v;
        }
        __syncthreads();

        const float* B = (seg < 3) ? (const float*)(g_G + (size_t)seg * Dd * OUTD)
                                   : (const float*)g_Gx;
        for (int kc = 0; kc < 8; ++kc) {
            {
                int kr = tid >> 4, c4 = tid & 15;   // 256 threads == 256 float4s
                reinterpret_cast<float4*>(&Ws[kr * 64])[c4] =
                    reinterpret_cast<const float4*>(B + (size_t)(kc * 16 + kr) * OUTD)[c4];
            }
            __syncthreads();
#pragma unroll
            for (int k = 0; k < 16; ++k) {
                float a[4];
#pragma unroll
                for (int i = 0; i < 4; ++i) a[i] = As[(ty * 4 + i) * 132 + kc * 16 + k];
                float4 w = *reinterpret_cast<float4*>(&Ws[k * 64 + tx * 4]);
#pragma unroll
                for (int i = 0; i < 4; ++i) {
                    acc[i][0] += a[i] * w.x; acc[i][1] += a[i] * w.y;
                    acc[i][2] += a[i] * w.z; acc[i][3] += a[i] * w.w;
                }
            }
            __syncthreads();
        }
    }

#pragma unroll
    for (int i = 0; i < 4; ++i) {
        int n = n0 + ty * 4 + i;
        if (n < Nn) {
            float4 o;
            o.x = acc[i][0] + g_c[tx * 4 + 0];
            o.y = acc[i][1] + g_c[tx * 4 + 1];
            o.z = acc[i][2] + g_c[tx * 4 + 2];
            o.w = acc[i][3] + g_c[tx * 4 + 3];
            *reinterpret_cast<float4*>(out + (size_t)n * OUTD + tx * 4) = o;
        }
    }
}

// ---------------- launch ------------------------------------------------------
extern "C" void kernel_launch(void* const* d_in, const int* in_sizes, int n_in,
                              void* d_out, int out_size) {
    const float* x    = (const float*)d_in[0];
    const int*   src  = (const int*)  d_in[1];
    const int*   dst  = (const int*)  d_in[2];
    const float* W1   = (const float*)d_in[3];
    const float* b1   = (const float*)d_in[4];
    const float* W2   = (const float*)d_in[5];
    const float* b2   = (const float*)d_in[6];
    const float* Wlin = (const float*)d_in[7];
    const float* blin = (const float*)d_in[8];
    float* out = (float*)d_out;

    k_init<<<(Rr * Nn + 255) / 256, 256>>>();
    k_degree<<<(Rr * Ee + 255) / 256, 256>>>(src, dst);
    dim3 rsgrid((Nn + 255) / 256, Rr);
    k_rowstart<<<rsgrid, 256>>>();
    k_csrfill<<<(Rr * Ee + 255) / 256, 256>>>(src, dst);
    k_prep1<<<Rr * Dd, OUTD>>>(W2, Wlin);
    k_prep2<<<32, 256>>>(b2, Wlin, blin);

    k_node1<<<(Nn + 63) / 64, 256>>>(x, W1, b1);
    k_node2<<<(Nn + 63) / 64, 256>>>(x, out);
}